// round 1
// baseline (speedup 1.0000x reference)
#include <cuda_runtime.h>

#define DIMV 128
#define HIDV 128
#define BATCH 64
#define NQ 64
#define ND 64

typedef unsigned long long ull;

// Scratch for projections (device globals: no allocation allowed)
__device__ float g_hq[BATCH * NQ * HIDV];  // q @ W1[:128] + b1
__device__ float g_hd[BATCH * ND * HIDV];  // d @ W1[128:]

// ---- f32x2 packed helpers (Blackwell) ----
__device__ __forceinline__ ull pack2(float x, float y) {
    ull r; asm("mov.b64 %0, {%1,%2};" : "=l"(r) : "f"(x), "f"(y)); return r;
}
__device__ __forceinline__ void unpack2(ull v, float& x, float& y) {
    asm("mov.b64 {%0,%1}, %2;" : "=f"(x), "=f"(y) : "l"(v));
}
__device__ __forceinline__ ull fma2(ull a, ull b, ull c) {
    ull d; asm("fma.rn.f32x2 %0, %1, %2, %3;" : "=l"(d) : "l"(a), "l"(b), "l"(c)); return d;
}
__device__ __forceinline__ ull add2(ull a, ull b) {
    ull d; asm("add.rn.f32x2 %0, %1, %2;" : "=l"(d) : "l"(a), "l"(b)); return d;
}

// Mask dtype auto-detect: 0 = int32, 1 = uint8, 2 = float32
__device__ __forceinline__ bool mask_at(const void* p, int i, int mode) {
    if (mode == 0) return ((const int*)p)[i] != 0;
    if (mode == 2) return ((const float*)p)[i] != 0.0f;
    return ((const unsigned char*)p)[i] != 0;
}

// ============================================================================
// Kernel 1: projections. grid = 128 blocks = (batch, side). side0 -> hq (+b1),
// side1 -> hd. Block computes 64 rows x 128 cols. Thread tile: 4n x 16h.
// X staged transposed [d][n] (pad 68) to avoid 128-stride bank conflicts.
// W staged [d][h] (pad 132).
// ============================================================================
__global__ void __launch_bounds__(128, 1)
proj_kernel(const float* __restrict__ query, const float* __restrict__ doc,
            const float* __restrict__ W1, const float* __restrict__ b1)
{
    extern __shared__ float sm[];
    float* Xs  = sm;                      // [128][68] transposed
    float* Ws  = sm + 128 * 68;           // [128][132]
    float* b1s = Ws + 128 * 132;          // [128]

    const int tid  = threadIdx.x;
    const int side = blockIdx.x & 1;
    const int b    = blockIdx.x >> 1;

    const float* X  = (side ? doc : query) + b * 64 * DIMV;
    const float* Wg = W1 + side * DIMV * HIDV;

    // Stage X transposed
    for (int i = tid; i < 64 * 32; i += 128) {
        int n = i >> 5, seg = i & 31;
        float4 v = ((const float4*)X)[n * 32 + seg];
        int d = seg * 4;
        Xs[(d + 0) * 68 + n] = v.x;
        Xs[(d + 1) * 68 + n] = v.y;
        Xs[(d + 2) * 68 + n] = v.z;
        Xs[(d + 3) * 68 + n] = v.w;
    }
    // Stage W
    for (int i = tid; i < 128 * 32; i += 128) {
        int d = i >> 5, seg = i & 31;
        *(float4*)(Ws + d * 132 + seg * 4) = ((const float4*)Wg)[d * 32 + seg];
    }
    if (tid < 128) b1s[tid] = b1[tid];
    __syncthreads();

    const int hgrp = tid & 7;    // h base = hgrp*16
    const int ngrp = tid >> 3;   // n base = ngrp*4

    ull acc[4][8];
#pragma unroll
    for (int r = 0; r < 4; r++)
#pragma unroll
        for (int j = 0; j < 8; j++) acc[r][j] = 0ull;

    const float* wbase = Ws + hgrp * 16;
    const float* xbase = Xs + ngrp * 4;

#pragma unroll 2
    for (int d = 0; d < 128; d++) {
        float x0 = xbase[d * 68 + 0];
        float x1 = xbase[d * 68 + 1];
        float x2 = xbase[d * 68 + 2];
        float x3 = xbase[d * 68 + 3];
        const ulonglong2* wr = (const ulonglong2*)(wbase + d * 132);
        ulonglong2 wa = wr[0], wb = wr[1], wc = wr[2], wd = wr[3];
        ull w[8] = {wa.x, wa.y, wb.x, wb.y, wc.x, wc.y, wd.x, wd.y};
        ull xp[4] = {pack2(x0, x0), pack2(x1, x1), pack2(x2, x2), pack2(x3, x3)};
#pragma unroll
        for (int r = 0; r < 4; r++)
#pragma unroll
            for (int j = 0; j < 8; j++)
                acc[r][j] = fma2(xp[r], w[j], acc[r][j]);
    }

    float* gout = (side ? g_hd : g_hq) + (b * 64 + ngrp * 4) * HIDV + hgrp * 16;
#pragma unroll
    for (int r = 0; r < 4; r++) {
        float v[16];
#pragma unroll
        for (int j = 0; j < 8; j++) unpack2(acc[r][j], v[2 * j], v[2 * j + 1]);
        if (side == 0) {
#pragma unroll
            for (int k = 0; k < 16; k++) v[k] += b1s[hgrp * 16 + k];
        }
#pragma unroll
        for (int q = 0; q < 4; q++)
            *(float4*)(gout + r * HIDV + q * 4) =
                make_float4(v[4 * q], v[4 * q + 1], v[4 * q + 2], v[4 * q + 3]);
    }
}

// ============================================================================
// Kernel 2: pairwise scores with separable mask compaction.
// grid = 128 blocks = (batch, m-half). Block: compact valid n (<=64) and valid
// m within its 32-m half (<=32), zero-fill its output region, then compute
// only valid pairs with 2n x 2m register tiles and packed f32x2 FMAs.
// ============================================================================
__global__ void __launch_bounds__(128, 1)
pair_kernel(const void* __restrict__ qmask, const void* __restrict__ dmask,
            const float* __restrict__ W2g, const float* __restrict__ b2g,
            float* __restrict__ out)
{
    extern __shared__ float sm[];
    float* hq_s = sm;                       // [64][132] compacted valid-n rows
    float* hd_s = sm + 64 * 132;            // [32][132] compacted valid-m rows
    float* w2_s = hd_s + 32 * 132;          // [3][128] transposed W2
    int* nlist = (int*)(w2_s + 3 * 128);    // 66
    int* mlist = nlist + 66;                // 34
    int* meta  = mlist + 34;                // [0]=nv [1]=mv [2]=notInt [3]=notF32

    const int tid  = threadIdx.x;
    const int lane = tid & 31;
    const int wid  = tid >> 5;
    const int half = blockIdx.x & 1;
    const int b    = blockIdx.x >> 1;

    if (tid < 4) meta[tid] = 0;
    __syncthreads();

    // ---- mask dtype detection (scan 512 words = safe under all candidate dtypes)
    {
        const unsigned* qw = (const unsigned*)qmask;
        int notInt = 0, notF32 = 0;
        for (int i = tid; i < 512; i += 128) {
            unsigned w = qw[i];
            if (w > 1u) notInt = 1;
            if (w != 0u && w != 0x3F800000u) notF32 = 1;
        }
        if (notInt) meta[2] = 1;
        if (notF32) meta[3] = 1;
    }
    __syncthreads();
    const int mode = (meta[2] == 0) ? 0 : ((meta[3] == 0) ? 2 : 1);

    // ---- build compacted index lists via ballot
    if (wid == 0) {
        bool v0 = mask_at(qmask, b * 64 + lane, mode);
        unsigned m0 = __ballot_sync(0xFFFFFFFFu, v0);
        bool v1 = mask_at(qmask, b * 64 + 32 + lane, mode);
        unsigned m1 = __ballot_sync(0xFFFFFFFFu, v1);
        unsigned lt = (1u << lane) - 1u;
        int c0 = __popc(m0);
        if (v0) nlist[__popc(m0 & lt)] = lane;
        if (v1) nlist[c0 + __popc(m1 & lt)] = 32 + lane;
        __syncwarp();
        if (lane == 0) {
            int nv = c0 + __popc(m1);
            meta[0] = nv;
            if (nv & 1) nlist[nv] = nlist[nv - 1];  // pad to even
        }
    }
    if (wid == 1) {
        int mb = half * 32;
        bool v = mask_at(dmask, b * 64 + mb + lane, mode);
        unsigned mm = __ballot_sync(0xFFFFFFFFu, v);
        unsigned lt = (1u << lane) - 1u;
        if (v) mlist[__popc(mm & lt)] = mb + lane;
        __syncwarp();
        if (lane == 0) {
            int mv = __popc(mm);
            meta[1] = mv;
            if (mv & 1) mlist[mv] = mlist[mv - 1];  // pad to even
        }
    }
    if (tid >= 64) {  // transpose-load W2 (128,3) -> w2_s[o][h]
        for (int i = tid - 64; i < 384; i += 64) {
            int h = i / 3, o = i - h * 3;
            w2_s[o * 128 + h] = W2g[i];
        }
    }
    __syncthreads();

    const int nv = meta[0], mv = meta[1];
    const int nvp = (nv + 1) & ~1, mvp = (mv + 1) & ~1;

    // ---- load compacted hq/hd rows into smem
    for (int i = tid; i < nvp * 32; i += 128) {
        int r = i >> 5, seg = i & 31;
        int gn = nlist[r];
        *(float4*)(hq_s + r * 132 + seg * 4) =
            *(const float4*)(g_hq + (b * 64 + gn) * HIDV + seg * 4);
    }
    for (int i = tid; i < mvp * 32; i += 128) {
        int r = i >> 5, seg = i & 31;
        int gm = mlist[r];
        *(float4*)(hd_s + r * 132 + seg * 4) =
            *(const float4*)(g_hd + (b * 64 + gm) * HIDV + seg * 4);
    }

    // ---- zero-fill this block's output region (out is poisoned by harness)
    float* obase = out + b * (64 * 64 * 3) + half * (32 * 3);
    for (int i = tid; i < 64 * 24; i += 128) {
        int n = i / 24, j = i - n * 24;
        ((float4*)(obase + n * 192))[j] = make_float4(0.f, 0.f, 0.f, 0.f);
    }
    __syncthreads();

    const float b2_0 = b2g[0], b2_1 = b2g[1], b2_2 = b2g[2];
    const int ntiles = nvp >> 1, mtiles = mvp >> 1;
    const int total = ntiles * mtiles;

    for (int t = tid; t < total; t += 128) {
        int ni = t / mtiles;
        int mi = t - ni * mtiles;
        const float* pa0 = hq_s + (2 * ni) * 132;
        const float* pa1 = pa0 + 132;
        const float* pd0 = hd_s + (2 * mi) * 132;
        const float* pd1 = pd0 + 132;

        ull acc[4][3];
#pragma unroll
        for (int c = 0; c < 4; c++)
#pragma unroll
            for (int o = 0; o < 3; o++) acc[c][o] = 0ull;

#define COMBO(c, Alo, Ahi, Dlo, Dhi) do {                                   \
            ull tlo = add2((Alo), (Dlo));                                    \
            ull thi = add2((Ahi), (Dhi));                                    \
            float f0, f1, f2, f3;                                            \
            unpack2(tlo, f0, f1); unpack2(thi, f2, f3);                      \
            f0 = fmaxf(f0, 0.f); f1 = fmaxf(f1, 0.f);                        \
            f2 = fmaxf(f2, 0.f); f3 = fmaxf(f3, 0.f);                        \
            tlo = pack2(f0, f1); thi = pack2(f2, f3);                        \
            acc[c][0] = fma2(tlo, w0.x, acc[c][0]);                          \
            acc[c][0] = fma2(thi, w0.y, acc[c][0]);                          \
            acc[c][1] = fma2(tlo, w1.x, acc[c][1]);                          \
            acc[c][1] = fma2(thi, w1.y, acc[c][1]);                          \
            acc[c][2] = fma2(tlo, w2v.x, acc[c][2]);                         \
            acc[c][2] = fma2(thi, w2v.y, acc[c][2]);                         \
        } while (0)

#pragma unroll 4
        for (int h = 0; h < 128; h += 4) {
            ulonglong2 A0 = *(const ulonglong2*)(pa0 + h);
            ulonglong2 A1 = *(const ulonglong2*)(pa1 + h);
            ulonglong2 D0 = *(const ulonglong2*)(pd0 + h);
            ulonglong2 D1 = *(const ulonglong2*)(pd1 + h);
            ulonglong2 w0  = *(const ulonglong2*)(w2_s + h);
            ulonglong2 w1  = *(const ulonglong2*)(w2_s + 128 + h);
            ulonglong2 w2v = *(const ulonglong2*)(w2_s + 256 + h);
            COMBO(0, A0.x, A0.y, D0.x, D0.y);
            COMBO(1, A0.x, A0.y, D1.x, D1.y);
            COMBO(2, A1.x, A1.y, D0.x, D0.y);
            COMBO(3, A1.x, A1.y, D1.x, D1.y);
        }
#undef COMBO

        const int gn0 = nlist[2 * ni], gn1 = nlist[2 * ni + 1];
        const int gm0 = mlist[2 * mi], gm1 = mlist[2 * mi + 1];

#define WRITE(c, gn, gm) do {                                               \
            float lo, hi, s0, s1, s2;                                        \
            unpack2(acc[c][0], lo, hi); s0 = lo + hi + b2_0;                 \
            unpack2(acc[c][1], lo, hi); s1 = lo + hi + b2_1;                 \
            unpack2(acc[c][2], lo, hi); s2 = lo + hi + b2_2;                 \
            float* po = out + (((b * 64 + (gn)) * 64 + (gm)) * 3);           \
            po[0] = s0; po[1] = s1; po[2] = s2;                              \
        } while (0)

        WRITE(0, gn0, gm0);
        WRITE(1, gn0, gm1);
        WRITE(2, gn1, gm0);
        WRITE(3, gn1, gm1);
#undef WRITE
    }
}

// ============================================================================
extern "C" void kernel_launch(void* const* d_in, const int* in_sizes, int n_in,
                              void* d_out, int out_size)
{
    const float* query = (const float*)d_in[0];
    const float* doc   = (const float*)d_in[1];
    const void*  qmask = d_in[2];
    const void*  dmask = d_in[3];
    const float* W1    = (const float*)d_in[4];
    const float* b1    = (const float*)d_in[5];
    const float* W2    = (const float*)d_in[6];
    const float* b2    = (const float*)d_in[7];
    float* out = (float*)d_out;

    const int sm1 = (128 * 68 + 128 * 132 + 128) * (int)sizeof(float);     // ~100.5 KB
    const int sm2 = (64 * 132 + 32 * 132 + 3 * 128) * (int)sizeof(float)
                    + (66 + 34 + 4) * (int)sizeof(int);                    // ~51.4 KB

    cudaFuncSetAttribute(proj_kernel, cudaFuncAttributeMaxDynamicSharedMemorySize, sm1);
    cudaFuncSetAttribute(pair_kernel, cudaFuncAttributeMaxDynamicSharedMemorySize, sm2);

    proj_kernel<<<128, 128, sm1>>>(query, doc, W1, b1);
    pair_kernel<<<128, 128, sm2>>>(qmask, dmask, W2, b2, out);
}